// round 12
// baseline (speedup 1.0000x reference)
#include <cuda_runtime.h>
#include <math.h>
#include <stdint.h>

#define BB   2
#define LL   2048
#define DD   1024
#define HH   16
#define KVH  4
#define DHH  64
#define GG   (HH / KVH)
#define MROWS (BB * LL)          // 4096

// ---------------- scratch (no allocations allowed) ----------------
__device__ float g_q [MROWS * HH * DHH];   // post-GEMM q (pre-rope)
__device__ float g_k [MROWS * KVH * DHH];  // post-GEMM k (pre-rope)
__device__ float g_v [MROWS * KVH * DHH];  // v (tf32-rounded)
__device__ float g_q2[MROWS * HH * DHH];   // rope'd, scaled, rounded, d-PERMUTED
__device__ float g_k2[MROWS * KVH * DHH];  // rope'd, rounded, d-PERMUTED
__device__ float g_att[MROWS * HH * DHH];  // attention out (tf32-rounded)
__device__ float g_xt [MROWS * DD];
__device__ float g_wqt[DD * HH * DHH];
__device__ float g_wkt[DD * KVH * DHH];
__device__ float g_wvt[DD * KVH * DHH];
__device__ float g_wot[HH * DHH * DD];

// ---------------- helpers ----------------
__device__ __forceinline__ uint32_t f2tf32(float f) {
    uint32_t u;
    asm("cvt.rna.tf32.f32 %0, %1;" : "=r"(u) : "f"(f));
    return u;
}
__device__ __forceinline__ float rnd_tf32(float f) {
    return __uint_as_float(f2tf32(f));
}

__device__ __forceinline__ void mma_tf32(float* d, const uint32_t* a, const uint32_t* b) {
    asm volatile(
        "mma.sync.aligned.m16n8k8.row.col.f32.tf32.tf32.f32 "
        "{%0,%1,%2,%3}, {%4,%5,%6,%7}, {%8,%9}, {%0,%1,%2,%3};\n"
        : "+f"(d[0]), "+f"(d[1]), "+f"(d[2]), "+f"(d[3])
        : "r"(a[0]), "r"(a[1]), "r"(a[2]), "r"(a[3]), "r"(b[0]), "r"(b[1]));
}

__device__ __forceinline__ uint32_t smaddr(const void* p) {
    return (uint32_t)__cvta_generic_to_shared(p);
}
__device__ __forceinline__ void cp_async16(uint32_t dst, const void* src) {
    asm volatile("cp.async.cg.shared.global [%0], [%1], 16;\n" :: "r"(dst), "l"(src));
}

// d-permutation within each 8-group: orig k -> phys 2*(k&3) + ((k>>2)&1)
__device__ __forceinline__ int dperm(int d) {
    return (d & ~7) | (((d & 3) << 1) | ((d >> 2) & 1));
}

// ---------------- prologue: tf32-round x and all weights ----------------
#define X4  (MROWS * DD / 4)
#define WQ4 (DD * HH * DHH / 4)
#define WK4 (DD * KVH * DHH / 4)
#define WV4 WK4
#define WO4 (HH * DHH * DD / 4)
#define TOT4 (X4 + WQ4 + WK4 + WV4 + WO4)

__global__ void round_inputs_kernel(const float4* __restrict__ x,
                                    const float4* __restrict__ wq,
                                    const float4* __restrict__ wk,
                                    const float4* __restrict__ wv,
                                    const float4* __restrict__ wo,
                                    float4* __restrict__ xt, float4* __restrict__ wqt,
                                    float4* __restrict__ wkt, float4* __restrict__ wvt,
                                    float4* __restrict__ wot) {
    int i = blockIdx.x * blockDim.x + threadIdx.x;
    if (i >= TOT4) return;
    const float4* s;
    float4* d;
    int j = i;
    if (j < X4)                    { s = x;  d = xt;  }
    else if ((j -= X4)  < WQ4)     { s = wq; d = wqt; }
    else if ((j -= WQ4) < WK4)     { s = wk; d = wkt; }
    else if ((j -= WK4) < WV4)     { s = wv; d = wvt; }
    else { j -= WV4;                 s = wo; d = wot; }
    float4 v = s[j];
    v.x = rnd_tf32(v.x); v.y = rnd_tf32(v.y);
    v.z = rnd_tf32(v.z); v.w = rnd_tf32(v.w);
    d[j] = v;
}

// ---------------- 2-stage cp.async tf32 GEMM core (CVT-free inner loop) ----------------
template <bool ROUND_OUT>
__device__ __forceinline__ void gemm_pipe_core(const float* __restrict__ A,
                                               const float* __restrict__ B,
                                               float* __restrict__ C,
                                               int K, int NB, int n0, int m0) {
    constexpr int BM = 128, BN = 64, BK = 32;
    constexpr int AST = BK + 4;   // 36
    constexpr int BST = BN + 8;   // 72
    extern __shared__ float smf[];
    float* Asb = smf;
    float* Bsb = smf + 2 * BM * AST;

    const int tid  = threadIdx.x;
    const int wid  = tid >> 5;
    const int lane = tid & 31;
    const int warpM = wid & 3;
    const int warpN = wid >> 2;
    const int g = lane >> 2;
    const int t = lane & 3;

    float acc[2][4][4];
#pragma unroll
    for (int i = 0; i < 2; ++i)
#pragma unroll
        for (int j = 0; j < 4; ++j)
#pragma unroll
            for (int r = 0; r < 4; ++r) acc[i][j][r] = 0.f;

    auto issue = [&](int k0, int buf) {
        float* As = Asb + buf * BM * AST;
        float* Bs = Bsb + buf * BK * BST;
#pragma unroll
        for (int i = tid; i < BM * BK / 4; i += 256) {
            int m  = i >> 3;
            int k4 = (i & 7) << 2;
            cp_async16(smaddr(&As[m * AST + k4]),
                       &A[(size_t)(m0 + m) * K + k0 + k4]);
        }
#pragma unroll
        for (int i = tid; i < BK * BN / 4; i += 256) {
            int kk = i >> 4;
            int n4 = (i & 15) << 2;
            cp_async16(smaddr(&Bs[kk * BST + n4]),
                       &B[(size_t)(k0 + kk) * NB + n0 + n4]);
        }
        asm volatile("cp.async.commit_group;\n");
    };

    issue(0, 0);
    int buf = 0;
    for (int k0 = 0; k0 < K; k0 += BK) {
        if (k0 + BK < K) {
            issue(k0 + BK, buf ^ 1);
            asm volatile("cp.async.wait_group 1;\n");
        } else {
            asm volatile("cp.async.wait_group 0;\n");
        }
        __syncthreads();

        const uint32_t* As = (const uint32_t*)(Asb + buf * BM * AST);
        const uint32_t* Bs = (const uint32_t*)(Bsb + buf * BK * BST);
#pragma unroll
        for (int ks = 0; ks < BK / 8; ++ks) {
            uint32_t af[2][4], bf[4][2];
#pragma unroll
            for (int mt = 0; mt < 2; ++mt) {
                int mrow = warpM * 32 + mt * 16 + g;
                int kb = ks * 8 + t;
                af[mt][0] = As[mrow * AST + kb];
                af[mt][1] = As[(mrow + 8) * AST + kb];
                af[mt][2] = As[mrow * AST + kb + 4];
                af[mt][3] = As[(mrow + 8) * AST + kb + 4];
            }
#pragma unroll
            for (int nt = 0; nt < 4; ++nt) {
                int ncol = warpN * 32 + nt * 8 + g;
                int kb = ks * 8 + t;
                bf[nt][0] = Bs[kb * BST + ncol];
                bf[nt][1] = Bs[(kb + 4) * BST + ncol];
            }
#pragma unroll
            for (int mt = 0; mt < 2; ++mt)
#pragma unroll
                for (int nt = 0; nt < 4; ++nt)
                    mma_tf32(acc[mt][nt], af[mt], bf[nt]);
        }
        __syncthreads();
        buf ^= 1;
    }

#pragma unroll
    for (int mt = 0; mt < 2; ++mt) {
#pragma unroll
        for (int nt = 0; nt < 4; ++nt) {
            int row = m0 + warpM * 32 + mt * 16 + g;
            int col = n0 + warpN * 32 + nt * 8 + t * 2;
            float c0 = acc[mt][nt][0], c1 = acc[mt][nt][1];
            float c2 = acc[mt][nt][2], c3 = acc[mt][nt][3];
            if (ROUND_OUT) {
                c0 = rnd_tf32(c0); c1 = rnd_tf32(c1);
                c2 = rnd_tf32(c2); c3 = rnd_tf32(c3);
            }
            *(float2*)&C[(size_t)row * NB + col]       = make_float2(c0, c1);
            *(float2*)&C[(size_t)(row + 8) * NB + col] = make_float2(c2, c3);
        }
    }
}

#define GEMM_SMEM ((2 * 128 * 36 + 2 * 32 * 72) * 4)   // 55296 B

__global__ __launch_bounds__(256)
void gemm_qkv_kernel(const float* __restrict__ x,
                     const float* __restrict__ Wq, const float* __restrict__ Wk,
                     const float* __restrict__ Wv,
                     float* __restrict__ q, float* __restrict__ k,
                     float* __restrict__ v) {
    const int nt = blockIdx.x;
    const float* B;
    float* C;
    int NB, n0;
    if (nt < 16)      { B = Wq; C = q; NB = 1024; n0 = nt * 64; }
    else if (nt < 20) { B = Wk; C = k; NB = 256;  n0 = (nt - 16) * 64; }
    else              { B = Wv; C = v; NB = 256;  n0 = (nt - 20) * 64; }
    gemm_pipe_core<true>(x, B, C, DD, NB, n0, blockIdx.y * 128);
}

__global__ __launch_bounds__(256)
void gemm_wo_kernel(const float* __restrict__ A, const float* __restrict__ B,
                    float* __restrict__ C, int K, int NB) {
    gemm_pipe_core<false>(A, B, C, K, NB, blockIdx.x * 64, blockIdx.y * 128);
}

// ---------------- RoPE: read g_q/g_k, write PERMUTED g_q2/g_k2 ----------------
#define QSCALE (0.125f * 1.4426950408889634f)   // softmax scale * log2(e)

__global__ void rope2_kernel(const float* __restrict__ qi, const float* __restrict__ ki,
                             float* __restrict__ qo, float* __restrict__ ko,
                             const float* __restrict__ cosb,
                             const float* __restrict__ sinb) {
    const int qtot = BB * LL * HH * (DHH / 2);
    const int ktot = BB * LL * KVH * (DHH / 2);
    int i = blockIdx.x * blockDim.x + threadIdx.x;
    const float* src;
    float* dst;
    int heads, j;
    float oscale;
    if (i < qtot)             { src = qi; dst = qo; heads = HH;  j = i;        oscale = QSCALE; }
    else if (i < qtot + ktot) { src = ki; dst = ko; heads = KVH; j = i - qtot; oscale = 1.f; }
    else return;
    int d = j & 31;
    int h = (j >> 5) % heads;
    int l = (j >> 5) / heads % LL;
    int b = (j >> 5) / heads / LL;
    size_t base = ((size_t)((b * LL + l) * heads + h)) * DHH;
    float c = cosb[l * (DHH / 2) + d];
    float s = sinb[l * (DHH / 2) + d];
    float t1 = src[base + d];
    float t2 = src[base + d + DHH / 2];
    int pd = dperm(d);                      // perm stays within the 8-group
    dst[base + pd]           = rnd_tf32((t1 * c - t2 * s) * oscale);
    dst[base + pd + DHH / 2] = rnd_tf32((t2 * c + t1 * s) * oscale);
}

// ---------------- tf32 flash attention: DOUBLE-BUFFERED cp.async K/V ----------------
// SMEM: 2 x (Ks[64][72] + Vs[64][72]) = 73728 B -> 3 blocks/SM.
// P overwrites the CURRENT K buffer after S-phase (in-flight load targets the other).
#define KST 72
#define VST 72
#define ATTN_SMEM ((2 * 64 * KST + 2 * 64 * VST) * 4)   // 73728 B

__global__ __launch_bounds__(128)
void attn_mma_kernel(const float* __restrict__ q, const float* __restrict__ k,
                     const float* __restrict__ v, float* __restrict__ o) {
    extern __shared__ uint32_t sm[];
    uint32_t* Kb[2] = { sm, sm + 64 * KST };
    uint32_t* Vb[2] = { sm + 2 * 64 * KST, sm + 2 * 64 * KST + 64 * VST };

    const int bx  = gridDim.x - 1 - blockIdx.x;   // longest first
    const int bh  = blockIdx.y;
    const int b   = bh / HH;
    const int h   = bh % HH;
    const int kvh = h / GG;
    const int q0  = bx * 64;
    const int tid = threadIdx.x;
    const int wid = tid >> 5;
    const int lane = tid & 31;
    const int g = lane >> 2;
    const int t = lane & 3;

    // ---- stage Q tile (pre-scaled/rounded/permuted) through Kb[0], extract fragments
    const uint4* qbase = (const uint4*)(q + ((size_t)((b * LL + q0) * HH + h)) * DHH);
#pragma unroll
    for (int i = tid; i < 64 * 64 / 4; i += 128) {
        int row = i >> 4;
        int c4  = i & 15;
        *(uint4*)&Kb[0][row * KST + c4 * 4] = qbase[row * (HH * DHH / 4) + c4];
    }
    __syncthreads();

    uint32_t qf[8][4];
    {
        int r0 = wid * 16 + g;
#pragma unroll
        for (int ks = 0; ks < 8; ++ks) {
            uint2 u = *(const uint2*)&Kb[0][r0 * KST + ks * 8 + 2 * t];
            uint2 w = *(const uint2*)&Kb[0][(r0 + 8) * KST + ks * 8 + 2 * t];
            qf[ks][0] = u.x;
            qf[ks][2] = u.y;
            qf[ks][1] = w.x;
            qf[ks][3] = w.y;
        }
    }
    __syncthreads();     // everyone has Q fragments before Kb[0] is reused

    float o_acc[8][4];
#pragma unroll
    for (int nt = 0; nt < 8; ++nt)
#pragma unroll
        for (int r = 0; r < 4; ++r) o_acc[nt][r] = 0.f;
    float m0 = -INFINITY, m1 = -INFINITY, l0 = 0.f, l1 = 0.f;

    const float* kbase = k + ((size_t)b * LL * KVH + kvh) * DHH;
    const float* vbase = v + ((size_t)b * LL * KVH + kvh) * DHH;
    const int ntiles = bx + 1;
    const int perm0 = (t & 1) * 4 + (t >> 1);

    auto issueKV = [&](int kb, int buf) {
#pragma unroll
        for (int i = tid; i < 64 * 64 / 4; i += 128) {
            int row = i >> 4;
            int c4  = i & 15;
            size_t goff = (size_t)(kb + row) * KVH * DHH + c4 * 4;
            cp_async16(smaddr(&Kb[buf][row * KST + c4 * 4]), &kbase[goff]);
            cp_async16(smaddr(&Vb[buf][row * VST + c4 * 4]), &vbase[goff]);
        }
        asm volatile("cp.async.commit_group;\n");
    };

    issueKV(0, 0);

    for (int ti = 0; ti < ntiles; ++ti) {
        const int cur = ti & 1;
        // issue next tile's loads into the other buffer (drained at ti-1's end)
        if (ti + 1 < ntiles) {
            issueKV((ti + 1) * 64, cur ^ 1);
            asm volatile("cp.async.wait_group 1;\n");
        } else {
            asm volatile("cp.async.wait_group 0;\n");
        }
        __syncthreads();
        const uint32_t* Ks = Kb[cur];
        const uint32_t* Vs = Vb[cur];
        uint32_t* Pw = Kb[cur] + wid * 16 * KST;

        // ---- S' = Qs @ K^T (log2 domain); B fragments via LDS.64
        float s_acc[8][4];
#pragma unroll
        for (int nt = 0; nt < 8; ++nt)
#pragma unroll
            for (int r = 0; r < 4; ++r) s_acc[nt][r] = 0.f;
#pragma unroll
        for (int ks = 0; ks < 8; ++ks) {
            uint32_t bfr[8][2];
#pragma unroll
            for (int nt = 0; nt < 8; ++nt) {
                uint2 w = *(const uint2*)&Ks[(nt * 8 + g) * KST + ks * 8 + 2 * t];
                bfr[nt][0] = w.x;
                bfr[nt][1] = w.y;
            }
#pragma unroll
            for (int nt = 0; nt < 8; ++nt) mma_tf32(s_acc[nt], qf[ks], bfr[nt]);
        }

        const int wr = wid * 16 + g;
        if (ti == ntiles - 1) {
#pragma unroll
            for (int nt = 0; nt < 8; ++nt) {
                int c = nt * 8 + 2 * t;
                if (c > wr)          s_acc[nt][0] = -INFINITY;
                if (c + 1 > wr)      s_acc[nt][1] = -INFINITY;
                if (c > wr + 8)      s_acc[nt][2] = -INFINITY;
                if (c + 1 > wr + 8)  s_acc[nt][3] = -INFINITY;
            }
        }

        // ---- online softmax in exp2 domain
        float tm0 = -INFINITY, tm1 = -INFINITY;
#pragma unroll
        for (int nt = 0; nt < 8; ++nt) {
            tm0 = fmaxf(tm0, fmaxf(s_acc[nt][0], s_acc[nt][1]));
            tm1 = fmaxf(tm1, fmaxf(s_acc[nt][2], s_acc[nt][3]));
        }
        tm0 = fmaxf(tm0, __shfl_xor_sync(0xffffffff, tm0, 1));
        tm0 = fmaxf(tm0, __shfl_xor_sync(0xffffffff, tm0, 2));
        tm1 = fmaxf(tm1, __shfl_xor_sync(0xffffffff, tm1, 1));
        tm1 = fmaxf(tm1, __shfl_xor_sync(0xffffffff, tm1, 2));
        float mn0 = fmaxf(m0, tm0), mn1 = fmaxf(m1, tm1);
        float a0 = exp2f(m0 - mn0), a1 = exp2f(m1 - mn1);
        float ps0 = 0.f, ps1 = 0.f;
#pragma unroll
        for (int nt = 0; nt < 8; ++nt) {
            s_acc[nt][0] = exp2f(s_acc[nt][0] - mn0);
            s_acc[nt][1] = exp2f(s_acc[nt][1] - mn0);
            s_acc[nt][2] = exp2f(s_acc[nt][2] - mn1);
            s_acc[nt][3] = exp2f(s_acc[nt][3] - mn1);
            ps0 += s_acc[nt][0] + s_acc[nt][1];
            ps1 += s_acc[nt][2] + s_acc[nt][3];
        }
        ps0 += __shfl_xor_sync(0xffffffff, ps0, 1);
        ps0 += __shfl_xor_sync(0xffffffff, ps0, 2);
        ps1 += __shfl_xor_sync(0xffffffff, ps1, 1);
        ps1 += __shfl_xor_sync(0xffffffff, ps1, 2);
        l0 = l0 * a0 + ps0;
        l1 = l1 * a1 + ps1;
        m0 = mn0; m1 = mn1;

        __syncthreads();   // all warps done reading Ks before P overwrite

        // ---- write P into Kb[cur] (warp-private slice) at PERMUTED columns
#pragma unroll
        for (int nt = 0; nt < 8; ++nt) {
            int cp0 = nt * 8 + perm0;
            Pw[g * KST + cp0]           = f2tf32(s_acc[nt][0]);
            Pw[g * KST + cp0 + 2]       = f2tf32(s_acc[nt][1]);
            Pw[(g + 8) * KST + cp0]     = f2tf32(s_acc[nt][2]);
            Pw[(g + 8) * KST + cp0 + 2] = f2tf32(s_acc[nt][3]);
        }
        __syncwarp();

        // ---- rescale O, then O += P @ V
#pragma unroll
        for (int nt = 0; nt < 8; ++nt) {
            o_acc[nt][0] *= a0; o_acc[nt][1] *= a0;
            o_acc[nt][2] *= a1; o_acc[nt][3] *= a1;
        }
#pragma unroll
        for (int ks = 0; ks < 8; ++ks) {
            uint32_t pf[4];
            {
                uint2 p0 = *(const uint2*)&Pw[g * KST + ks * 8 + 2 * t];
                uint2 p1 = *(const uint2*)&Pw[(g + 8) * KST + ks * 8 + 2 * t];
                pf[0] = p0.x;
                pf[2] = p0.y;
                pf[1] = p1.x;
                pf[3] = p1.y;
            }
            uint32_t bv[8][2];
#pragma unroll
            for (int nt = 0; nt < 8; ++nt) {
                bv[nt][0] = Vs[(ks * 8 + t) * VST + nt * 8 + g];
                bv[nt][1] = Vs[(ks * 8 + t + 4) * VST + nt * 8 + g];
            }
#pragma unroll
            for (int nt = 0; nt < 8; ++nt) mma_tf32(o_acc[nt], pf, bv[nt]);
        }
        __syncthreads();   // buffer fully drained before it is re-targeted
    }

    // ---- epilogue (round att outputs so gemm_wo is CVT-free)
    const float inv0 = 1.f / l0, inv1 = 1.f / l1;
    const int row0 = q0 + wid * 16 + g;
    float* obase  = o + ((size_t)((b * LL + row0) * HH + h)) * DHH;
    float* obase8 = o + ((size_t)((b * LL + row0 + 8) * HH + h)) * DHH;
#pragma unroll
    for (int nt = 0; nt < 8; ++nt) {
        int c = nt * 8 + 2 * t;
        *(float2*)&obase[c]  = make_float2(rnd_tf32(o_acc[nt][0] * inv0),
                                           rnd_tf32(o_acc[nt][1] * inv0));
        *(float2*)&obase8[c] = make_float2(rnd_tf32(o_acc[nt][2] * inv1),
                                           rnd_tf32(o_acc[nt][3] * inv1));
    }
}

// ---------------- launch ----------------
extern "C" void kernel_launch(void* const* d_in, const int* in_sizes, int n_in,
                              void* d_out, int out_size) {
    const float* x  = (const float*)d_in[0];
    const float* rc = (const float*)d_in[1];
    const float* rs = (const float*)d_in[2];
    const float* Wq = (const float*)d_in[3];
    const float* Wk = (const float*)d_in[4];
    const float* Wv = (const float*)d_in[5];
    const float* Wo = (const float*)d_in[6];
    float* out = (float*)d_out;

    float *q, *k, *v, *q2, *k2, *att, *xt, *wqt, *wkt, *wvt, *wot;
    cudaGetSymbolAddress((void**)&q,   g_q);
    cudaGetSymbolAddress((void**)&k,   g_k);
    cudaGetSymbolAddress((void**)&v,   g_v);
    cudaGetSymbolAddress((void**)&q2,  g_q2);
    cudaGetSymbolAddress((void**)&k2,  g_k2);
    cudaGetSymbolAddress((void**)&att, g_att);
    cudaGetSymbolAddress((void**)&xt,  g_xt);
    cudaGetSymbolAddress((void**)&wqt, g_wqt);
    cudaGetSymbolAddress((void**)&wkt, g_wkt);
    cudaGetSymbolAddress((void**)&wvt, g_wvt);
    cudaGetSymbolAddress((void**)&wot, g_wot);

    static bool attr_set = false;
    if (!attr_set) {
        cudaFuncSetAttribute(gemm_qkv_kernel,
                             cudaFuncAttributeMaxDynamicSharedMemorySize, GEMM_SMEM);
        cudaFuncSetAttribute(gemm_wo_kernel,
                             cudaFuncAttributeMaxDynamicSharedMemorySize, GEMM_SMEM);
        cudaFuncSetAttribute(attn_mma_kernel,
                             cudaFuncAttributeMaxDynamicSharedMemorySize, ATTN_SMEM);
        attr_set = true;
    }

    // prologue: tf32-round x + weights
    round_inputs_kernel<<<(TOT4 + 255) / 256, 256>>>(
        (const float4*)x, (const float4*)Wq, (const float4*)Wk,
        (const float4*)Wv, (const float4*)Wo,
        (float4*)xt, (float4*)wqt, (float4*)wkt, (float4*)wvt, (float4*)wot);

    // merged QKV projection (outputs tf32-rounded)
    gemm_qkv_kernel<<<dim3(24, MROWS / 128), 256, GEMM_SMEM>>>(xt, wqt, wkt, wvt, q, k, v);

    // RoPE: q,k -> q2,k2 (scaled, rounded, d-permuted)
    {
        int tot = BB * LL * (HH + KVH) * (DHH / 2);
        rope2_kernel<<<(tot + 255) / 256, 256>>>(q, k, q2, k2, rc, rs);
    }

    // attention (reads permuted q2/k2, natural v)
    attn_mma_kernel<<<dim3(LL / 64, BB * HH), 128, ATTN_SMEM>>>(q2, k2, v, att);

    // output projection -> d_out
    gemm_wo_kernel<<<dim3(DD / 64, MROWS / 128), 256, GEMM_SMEM>>>(att, wot, out, DD, DD);
}

// round 13
// speedup vs baseline: 1.0056x; 1.0056x over previous
#include <cuda_runtime.h>
#include <math.h>
#include <stdint.h>

#define BB   2
#define LL   2048
#define DD   1024
#define HH   16
#define KVH  4
#define DHH  64
#define GG   (HH / KVH)
#define MROWS (BB * LL)          // 4096

// ---------------- scratch (no allocations allowed) ----------------
__device__ float g_q [MROWS * HH * DHH];   // post-GEMM q (pre-rope)
__device__ float g_k [MROWS * KVH * DHH];  // post-GEMM k (pre-rope)
__device__ float g_v [MROWS * KVH * DHH];  // v (tf32-rounded)
__device__ float g_q2[MROWS * HH * DHH];   // rope'd, scaled, rounded, d-PERMUTED
__device__ float g_k2[MROWS * KVH * DHH];  // rope'd, rounded, d-PERMUTED
__device__ float g_att[MROWS * HH * DHH];  // attention out (tf32-rounded)
__device__ float g_xt [MROWS * DD];
__device__ float g_wqt[DD * HH * DHH];
__device__ float g_wkt[DD * KVH * DHH];
__device__ float g_wvt[DD * KVH * DHH];
__device__ float g_wot[HH * DHH * DD];

// ---------------- helpers ----------------
__device__ __forceinline__ uint32_t f2tf32(float f) {
    uint32_t u;
    asm("cvt.rna.tf32.f32 %0, %1;" : "=r"(u) : "f"(f));
    return u;
}
__device__ __forceinline__ float rnd_tf32(float f) {
    return __uint_as_float(f2tf32(f));
}

__device__ __forceinline__ void mma_tf32(float* d, const uint32_t* a, const uint32_t* b) {
    asm volatile(
        "mma.sync.aligned.m16n8k8.row.col.f32.tf32.tf32.f32 "
        "{%0,%1,%2,%3}, {%4,%5,%6,%7}, {%8,%9}, {%0,%1,%2,%3};\n"
        : "+f"(d[0]), "+f"(d[1]), "+f"(d[2]), "+f"(d[3])
        : "r"(a[0]), "r"(a[1]), "r"(a[2]), "r"(a[3]), "r"(b[0]), "r"(b[1]));
}

__device__ __forceinline__ uint32_t smaddr(const void* p) {
    return (uint32_t)__cvta_generic_to_shared(p);
}
__device__ __forceinline__ void cp_async16(uint32_t dst, const void* src) {
    asm volatile("cp.async.cg.shared.global [%0], [%1], 16;\n" :: "r"(dst), "l"(src));
}

// d-permutation within each 8-group: orig k -> phys 2*(k&3) + ((k>>2)&1)
__device__ __forceinline__ int dperm(int d) {
    return (d & ~7) | (((d & 3) << 1) | ((d >> 2) & 1));
}

// ---------------- prologue: tf32-round x and all weights ----------------
#define X4  (MROWS * DD / 4)
#define WQ4 (DD * HH * DHH / 4)
#define WK4 (DD * KVH * DHH / 4)
#define WV4 WK4
#define WO4 (HH * DHH * DD / 4)
#define TOT4 (X4 + WQ4 + WK4 + WV4 + WO4)

__global__ void round_inputs_kernel(const float4* __restrict__ x,
                                    const float4* __restrict__ wq,
                                    const float4* __restrict__ wk,
                                    const float4* __restrict__ wv,
                                    const float4* __restrict__ wo,
                                    float4* __restrict__ xt, float4* __restrict__ wqt,
                                    float4* __restrict__ wkt, float4* __restrict__ wvt,
                                    float4* __restrict__ wot) {
    int i = blockIdx.x * blockDim.x + threadIdx.x;
    if (i >= TOT4) return;
    const float4* s;
    float4* d;
    int j = i;
    if (j < X4)                    { s = x;  d = xt;  }
    else if ((j -= X4)  < WQ4)     { s = wq; d = wqt; }
    else if ((j -= WQ4) < WK4)     { s = wk; d = wkt; }
    else if ((j -= WK4) < WV4)     { s = wv; d = wvt; }
    else { j -= WV4;                 s = wo; d = wot; }
    float4 v = s[j];
    v.x = rnd_tf32(v.x); v.y = rnd_tf32(v.y);
    v.z = rnd_tf32(v.z); v.w = rnd_tf32(v.w);
    d[j] = v;
}

// ---------------- 2-stage cp.async tf32 GEMM core (CVT-free inner loop) ----------------
template <bool ROUND_OUT>
__device__ __forceinline__ void gemm_pipe_core(const float* __restrict__ A,
                                               const float* __restrict__ B,
                                               float* __restrict__ C,
                                               int K, int NB, int n0, int m0) {
    constexpr int BM = 128, BN = 64, BK = 32;
    constexpr int AST = BK + 4;   // 36
    constexpr int BST = BN + 8;   // 72
    extern __shared__ float smf[];
    float* Asb = smf;
    float* Bsb = smf + 2 * BM * AST;

    const int tid  = threadIdx.x;
    const int wid  = tid >> 5;
    const int lane = tid & 31;
    const int warpM = wid & 3;
    const int warpN = wid >> 2;
    const int g = lane >> 2;
    const int t = lane & 3;

    float acc[2][4][4];
#pragma unroll
    for (int i = 0; i < 2; ++i)
#pragma unroll
        for (int j = 0; j < 4; ++j)
#pragma unroll
            for (int r = 0; r < 4; ++r) acc[i][j][r] = 0.f;

    auto issue = [&](int k0, int buf) {
        float* As = Asb + buf * BM * AST;
        float* Bs = Bsb + buf * BK * BST;
#pragma unroll
        for (int i = tid; i < BM * BK / 4; i += 256) {
            int m  = i >> 3;
            int k4 = (i & 7) << 2;
            cp_async16(smaddr(&As[m * AST + k4]),
                       &A[(size_t)(m0 + m) * K + k0 + k4]);
        }
#pragma unroll
        for (int i = tid; i < BK * BN / 4; i += 256) {
            int kk = i >> 4;
            int n4 = (i & 15) << 2;
            cp_async16(smaddr(&Bs[kk * BST + n4]),
                       &B[(size_t)(k0 + kk) * NB + n0 + n4]);
        }
        asm volatile("cp.async.commit_group;\n");
    };

    issue(0, 0);
    int buf = 0;
    for (int k0 = 0; k0 < K; k0 += BK) {
        if (k0 + BK < K) {
            issue(k0 + BK, buf ^ 1);
            asm volatile("cp.async.wait_group 1;\n");
        } else {
            asm volatile("cp.async.wait_group 0;\n");
        }
        __syncthreads();

        const uint32_t* As = (const uint32_t*)(Asb + buf * BM * AST);
        const uint32_t* Bs = (const uint32_t*)(Bsb + buf * BK * BST);
#pragma unroll
        for (int ks = 0; ks < BK / 8; ++ks) {
            uint32_t af[2][4], bf[4][2];
#pragma unroll
            for (int mt = 0; mt < 2; ++mt) {
                int mrow = warpM * 32 + mt * 16 + g;
                int kb = ks * 8 + t;
                af[mt][0] = As[mrow * AST + kb];
                af[mt][1] = As[(mrow + 8) * AST + kb];
                af[mt][2] = As[mrow * AST + kb + 4];
                af[mt][3] = As[(mrow + 8) * AST + kb + 4];
            }
#pragma unroll
            for (int nt = 0; nt < 4; ++nt) {
                int ncol = warpN * 32 + nt * 8 + g;
                int kb = ks * 8 + t;
                bf[nt][0] = Bs[kb * BST + ncol];
                bf[nt][1] = Bs[(kb + 4) * BST + ncol];
            }
#pragma unroll
            for (int mt = 0; mt < 2; ++mt)
#pragma unroll
                for (int nt = 0; nt < 4; ++nt)
                    mma_tf32(acc[mt][nt], af[mt], bf[nt]);
        }
        __syncthreads();
        buf ^= 1;
    }

#pragma unroll
    for (int mt = 0; mt < 2; ++mt) {
#pragma unroll
        for (int nt = 0; nt < 4; ++nt) {
            int row = m0 + warpM * 32 + mt * 16 + g;
            int col = n0 + warpN * 32 + nt * 8 + t * 2;
            float c0 = acc[mt][nt][0], c1 = acc[mt][nt][1];
            float c2 = acc[mt][nt][2], c3 = acc[mt][nt][3];
            if (ROUND_OUT) {
                c0 = rnd_tf32(c0); c1 = rnd_tf32(c1);
                c2 = rnd_tf32(c2); c3 = rnd_tf32(c3);
            }
            *(float2*)&C[(size_t)row * NB + col]       = make_float2(c0, c1);
            *(float2*)&C[(size_t)(row + 8) * NB + col] = make_float2(c2, c3);
        }
    }
}

#define GEMM_SMEM ((2 * 128 * 36 + 2 * 32 * 72) * 4)   // 55296 B

__global__ __launch_bounds__(256)
void gemm_qkv_kernel(const float* __restrict__ x,
                     const float* __restrict__ Wq, const float* __restrict__ Wk,
                     const float* __restrict__ Wv,
                     float* __restrict__ q, float* __restrict__ k,
                     float* __restrict__ v) {
    const int nt = blockIdx.x;
    const float* B;
    float* C;
    int NB, n0;
    if (nt < 16)      { B = Wq; C = q; NB = 1024; n0 = nt * 64; }
    else if (nt < 20) { B = Wk; C = k; NB = 256;  n0 = (nt - 16) * 64; }
    else              { B = Wv; C = v; NB = 256;  n0 = (nt - 20) * 64; }
    gemm_pipe_core<true>(x, B, C, DD, NB, n0, blockIdx.y * 128);
}

__global__ __launch_bounds__(256)
void gemm_wo_kernel(const float* __restrict__ A, const float* __restrict__ B,
                    float* __restrict__ C, int K, int NB) {
    gemm_pipe_core<false>(A, B, C, K, NB, blockIdx.x * 64, blockIdx.y * 128);
}

// ---------------- RoPE: read g_q/g_k, write PERMUTED g_q2/g_k2 ----------------
#define QSCALE (0.125f * 1.4426950408889634f)   // softmax scale * log2(e)

__global__ void rope2_kernel(const float* __restrict__ qi, const float* __restrict__ ki,
                             float* __restrict__ qo, float* __restrict__ ko,
                             const float* __restrict__ cosb,
                             const float* __restrict__ sinb) {
    const int qtot = BB * LL * HH * (DHH / 2);
    const int ktot = BB * LL * KVH * (DHH / 2);
    int i = blockIdx.x * blockDim.x + threadIdx.x;
    const float* src;
    float* dst;
    int heads, j;
    float oscale;
    if (i < qtot)             { src = qi; dst = qo; heads = HH;  j = i;        oscale = QSCALE; }
    else if (i < qtot + ktot) { src = ki; dst = ko; heads = KVH; j = i - qtot; oscale = 1.f; }
    else return;
    int d = j & 31;
    int h = (j >> 5) % heads;
    int l = (j >> 5) / heads % LL;
    int b = (j >> 5) / heads / LL;
    size_t base = ((size_t)((b * LL + l) * heads + h)) * DHH;
    float c = cosb[l * (DHH / 2) + d];
    float s = sinb[l * (DHH / 2) + d];
    float t1 = src[base + d];
    float t2 = src[base + d + DHH / 2];
    int pd = dperm(d);                      // perm stays within the 8-group
    dst[base + pd]           = rnd_tf32((t1 * c - t2 * s) * oscale);
    dst[base + pd + DHH / 2] = rnd_tf32((t2 * c + t1 * s) * oscale);
}

// ---------------- tf32 flash attention: KT=32 double-buffered cp.async ----------------
// SMEM: 2 x (K[32][72] + V[32][72]) = 36864 B -> 4 blocks/SM at 128 regs.
// P (64x32/tile; 16 rows/warp) overwrites the CURRENT 32-row K half.
#define KST 72
#define VST 72
#define KT  32
#define ATTN_SMEM ((2 * KT * KST + 2 * KT * VST) * 4)   // 36864 B

__global__ __launch_bounds__(128, 4)
void attn_mma_kernel(const float* __restrict__ q, const float* __restrict__ k,
                     const float* __restrict__ v, float* __restrict__ o) {
    extern __shared__ uint32_t sm[];
    uint32_t* Kb[2] = { sm, sm + KT * KST };
    uint32_t* Vb[2] = { sm + 2 * KT * KST, sm + 2 * KT * KST + KT * VST };

    const int bx  = gridDim.x - 1 - blockIdx.x;   // longest first
    const int bh  = blockIdx.y;
    const int b   = bh / HH;
    const int h   = bh % HH;
    const int kvh = h / GG;
    const int q0  = bx * 64;
    const int tid = threadIdx.x;
    const int wid = tid >> 5;
    const int lane = tid & 31;
    const int g = lane >> 2;
    const int t = lane & 3;

    // ---- stage Q tile (64x64, pre-scaled/rounded/permuted) through whole smem
    const uint4* qbase = (const uint4*)(q + ((size_t)((b * LL + q0) * HH + h)) * DHH);
#pragma unroll
    for (int i = tid; i < 64 * 64 / 4; i += 128) {
        int row = i >> 4;
        int c4  = i & 15;
        *(uint4*)&sm[row * KST + c4 * 4] = qbase[row * (HH * DHH / 4) + c4];
    }
    __syncthreads();

    uint32_t qf[8][4];
    {
        int r0 = wid * 16 + g;
#pragma unroll
        for (int ks = 0; ks < 8; ++ks) {
            uint2 u = *(const uint2*)&sm[r0 * KST + ks * 8 + 2 * t];
            uint2 w = *(const uint2*)&sm[(r0 + 8) * KST + ks * 8 + 2 * t];
            qf[ks][0] = u.x;
            qf[ks][2] = u.y;
            qf[ks][1] = w.x;
            qf[ks][3] = w.y;
        }
    }
    __syncthreads();     // everyone has Q fragments before smem is reused

    float o_acc[8][4];
#pragma unroll
    for (int nt = 0; nt < 8; ++nt)
#pragma unroll
        for (int r = 0; r < 4; ++r) o_acc[nt][r] = 0.f;
    float m0 = -INFINITY, m1 = -INFINITY, l0 = 0.f, l1 = 0.f;

    const float* kbase = k + ((size_t)b * LL * KVH + kvh) * DHH;
    const float* vbase = v + ((size_t)b * LL * KVH + kvh) * DHH;
    const int ntiles = (q0 + 64) / KT;            // 2*bx + 2
    const int perm0 = (t & 1) * 4 + (t >> 1);

    auto issueKV = [&](int kb, int buf) {
#pragma unroll
        for (int i = tid; i < KT * 64 / 4; i += 128) {   // 512 uint4 -> 4 iters
            int row = i >> 4;
            int c4  = i & 15;
            size_t goff = (size_t)(kb + row) * KVH * DHH + c4 * 4;
            cp_async16(smaddr(&Kb[buf][row * KST + c4 * 4]), &kbase[goff]);
            cp_async16(smaddr(&Vb[buf][row * VST + c4 * 4]), &vbase[goff]);
        }
        asm volatile("cp.async.commit_group;\n");
    };

    issueKV(0, 0);

    for (int ti = 0; ti < ntiles; ++ti) {
        const int cur = ti & 1;
        const int kb = ti * KT;
        // prefetch next tile into the other half (drained at end of ti-1)
        if (ti + 1 < ntiles) {
            issueKV((ti + 1) * KT, cur ^ 1);
            asm volatile("cp.async.wait_group 1;\n");
        } else {
            asm volatile("cp.async.wait_group 0;\n");
        }
        __syncthreads();
        const uint32_t* Ks = Kb[cur];
        const uint32_t* Vs = Vb[cur];
        uint32_t* Pw = Kb[cur] + wid * 16 * (KST / 2) * 0;  // placeholder, see below

        // ---- S' = Qs @ K^T : 4 key-groups of 8
        float s_acc[4][4];
#pragma unroll
        for (int nt = 0; nt < 4; ++nt)
#pragma unroll
            for (int r = 0; r < 4; ++r) s_acc[nt][r] = 0.f;
#pragma unroll
        for (int ks = 0; ks < 8; ++ks) {
            uint32_t bfr[4][2];
#pragma unroll
            for (int nt = 0; nt < 4; ++nt) {
                uint2 w = *(const uint2*)&Ks[(nt * 8 + g) * KST + ks * 8 + 2 * t];
                bfr[nt][0] = w.x;
                bfr[nt][1] = w.y;
            }
#pragma unroll
            for (int nt = 0; nt < 4; ++nt) mma_tf32(s_acc[nt], qf[ks], bfr[nt]);
        }

        // ---- causal mask (tiles with kb >= q0)
        const int wr = wid * 16 + g;
        const int dm = kb - q0;
        if (dm >= 0) {
#pragma unroll
            for (int nt = 0; nt < 4; ++nt) {
                int c = dm + nt * 8 + 2 * t;
                if (c > wr)          s_acc[nt][0] = -INFINITY;
                if (c + 1 > wr)      s_acc[nt][1] = -INFINITY;
                if (c > wr + 8)      s_acc[nt][2] = -INFINITY;
                if (c + 1 > wr + 8)  s_acc[nt][3] = -INFINITY;
            }
        }

        // ---- online softmax in exp2 domain
        float tm0 = -INFINITY, tm1 = -INFINITY;
#pragma unroll
        for (int nt = 0; nt < 4; ++nt) {
            tm0 = fmaxf(tm0, fmaxf(s_acc[nt][0], s_acc[nt][1]));
            tm1 = fmaxf(tm1, fmaxf(s_acc[nt][2], s_acc[nt][3]));
        }
        tm0 = fmaxf(tm0, __shfl_xor_sync(0xffffffff, tm0, 1));
        tm0 = fmaxf(tm0, __shfl_xor_sync(0xffffffff, tm0, 2));
        tm1 = fmaxf(tm1, __shfl_xor_sync(0xffffffff, tm1, 1));
        tm1 = fmaxf(tm1, __shfl_xor_sync(0xffffffff, tm1, 2));
        float mn0 = fmaxf(m0, tm0), mn1 = fmaxf(m1, tm1);
        float a0 = exp2f(m0 - mn0), a1 = exp2f(m1 - mn1);
        float ps0 = 0.f, ps1 = 0.f;
#pragma unroll
        for (int nt = 0; nt < 4; ++nt) {
            s_acc[nt][0] = exp2f(s_acc[nt][0] - mn0);
            s_acc[nt][1] = exp2f(s_acc[nt][1] - mn0);
            s_acc[nt][2] = exp2f(s_acc[nt][2] - mn1);
            s_acc[nt][3] = exp2f(s_acc[nt][3] - mn1);
            ps0 += s_acc[nt][0] + s_acc[nt][1];
            ps1 += s_acc[nt][2] + s_acc[nt][3];
        }
        ps0 += __shfl_xor_sync(0xffffffff, ps0, 1);
        ps0 += __shfl_xor_sync(0xffffffff, ps0, 2);
        ps1 += __shfl_xor_sync(0xffffffff, ps1, 1);
        ps1 += __shfl_xor_sync(0xffffffff, ps1, 2);
        l0 = l0 * a0 + ps0;
        l1 = l1 * a1 + ps1;
        m0 = mn0; m1 = mn1;

        __syncthreads();   // all warps done reading Ks before P overwrite

        // ---- write P (16 rows x 32 permuted cols per warp) into Kb[cur]
        // warp slice: rows [wid*8, wid*8+8) of the 32-row buffer at col offset 0/36
        // layout: Pw row r (0..15) -> Kb[cur][(wid*8 + (r&7))*KST + (r>>3)*36 + col]
        uint32_t* Pbase = Kb[cur] + wid * 8 * KST;
#pragma unroll
        for (int nt = 0; nt < 4; ++nt) {
            int cp0 = nt * 8 + perm0;
            // row g (0..7 -> half 0; 8..15 -> half 1 at +36)
            int half_g  = (g >> 3);
            int rg      = (g & 7);
            Pbase[rg * KST + half_g * 36 + cp0]     = f2tf32(s_acc[nt][0]);
            Pbase[rg * KST + half_g * 36 + cp0 + 2] = f2tf32(s_acc[nt][1]);
            // row g+8
            int g8 = g + 8;
            int half_g8 = (g8 >> 3);
            int rg8     = (g8 & 7);
            Pbase[rg8 * KST + half_g8 * 36 + cp0]     = f2tf32(s_acc[nt][2]);
            Pbase[rg8 * KST + half_g8 * 36 + cp0 + 2] = f2tf32(s_acc[nt][3]);
        }
        __syncwarp();

        // ---- rescale O, then O += P @ V  (4 key-groups of 8)
#pragma unroll
        for (int nt = 0; nt < 8; ++nt) {
            o_acc[nt][0] *= a0; o_acc[nt][1] *= a0;
            o_acc[nt][2] *= a1; o_acc[nt][3] *= a1;
        }
#pragma unroll
        for (int ks = 0; ks < 4; ++ks) {
            uint32_t pf[4];
            {
                // P row g: physical (wid*8 + (g&7)), col-half (g>>3)*36, key cols ks*8+2t
                uint2 p0 = *(const uint2*)&Pbase[(g & 7) * KST + (g >> 3) * 36 + ks * 8 + 2 * t];
                int g8 = g + 8;
                uint2 p1 = *(const uint2*)&Pbase[(g8 & 7) * KST + (g8 >> 3) * 36 + ks * 8 + 2 * t];
                pf[0] = p0.x;
                pf[2] = p0.y;
                pf[1] = p1.x;
                pf[3] = p1.y;
            }
            uint32_t bv[8][2];
#pragma unroll
            for (int nt = 0; nt < 8; ++nt) {
                bv[nt][0] = Vs[(ks * 8 + t) * VST + nt * 8 + g];
                bv[nt][1] = Vs[(ks * 8 + t + 4) * VST + nt * 8 + g];
            }
#pragma unroll
            for (int nt = 0; nt < 8; ++nt) mma_tf32(o_acc[nt], pf, bv[nt]);
        }
        __syncthreads();   // buffer fully drained before re-targeting
    }

    // ---- epilogue (round att outputs so gemm_wo is CVT-free)
    const float inv0 = 1.f / l0, inv1 = 1.f / l1;
    const int row0 = q0 + wid * 16 + g;
    float* obase  = o + ((size_t)((b * LL + row0) * HH + h)) * DHH;
    float* obase8 = o + ((size_t)((b * LL + row0 + 8) * HH + h)) * DHH;
#pragma unroll
    for (int nt = 0; nt < 8; ++nt) {
        int c = nt * 8 + 2 * t;
        *(float2*)&obase[c]  = make_float2(rnd_tf32(o_acc[nt][0] * inv0),
                                           rnd_tf32(o_acc[nt][1] * inv0));
        *(float2*)&obase8[c] = make_float2(rnd_tf32(o_acc[nt][2] * inv1),
                                           rnd_tf32(o_acc[nt][3] * inv1));
    }
}

// ---------------- launch ----------------
extern "C" void kernel_launch(void* const* d_in, const int* in_sizes, int n_in,
                              void* d_out, int out_size) {
    const float* x  = (const float*)d_in[0];
    const float* rc = (const float*)d_in[1];
    const float* rs = (const float*)d_in[2];
    const float* Wq = (const float*)d_in[3];
    const float* Wk = (const float*)d_in[4];
    const float* Wv = (const float*)d_in[5];
    const float* Wo = (const float*)d_in[6];
    float* out = (float*)d_out;

    float *q, *k, *v, *q2, *k2, *att, *xt, *wqt, *wkt, *wvt, *wot;
    cudaGetSymbolAddress((void**)&q,   g_q);
    cudaGetSymbolAddress((void**)&k,   g_k);
    cudaGetSymbolAddress((void**)&v,   g_v);
    cudaGetSymbolAddress((void**)&q2,  g_q2);
    cudaGetSymbolAddress((void**)&k2,  g_k2);
    cudaGetSymbolAddress((void**)&att, g_att);
    cudaGetSymbolAddress((void**)&xt,  g_xt);
    cudaGetSymbolAddress((void**)&wqt, g_wqt);
    cudaGetSymbolAddress((void**)&wkt, g_wkt);
    cudaGetSymbolAddress((void**)&wvt, g_wvt);
    cudaGetSymbolAddress((void**)&wot, g_wot);

    static bool attr_set = false;
    if (!attr_set) {
        cudaFuncSetAttribute(gemm_qkv_kernel,
                             cudaFuncAttributeMaxDynamicSharedMemorySize, GEMM_SMEM);
        cudaFuncSetAttribute(gemm_wo_kernel,
                             cudaFuncAttributeMaxDynamicSharedMemorySize, GEMM_SMEM);
        cudaFuncSetAttribute(attn_mma_kernel,
                             cudaFuncAttributeMaxDynamicSharedMemorySize, ATTN_SMEM);
        attr_set = true;
    }

    // prologue: tf32-round x + weights
    round_inputs_kernel<<<(TOT4 + 255) / 256, 256>>>(
        (const float4*)x, (const float4*)Wq, (const float4*)Wk,
        (const float4*)Wv, (const float4*)Wo,
        (float4*)xt, (float4*)wqt, (float4*)wkt, (float4*)wvt, (float4*)wot);

    // merged QKV projection (outputs tf32-rounded)
    gemm_qkv_kernel<<<dim3(24, MROWS / 128), 256, GEMM_SMEM>>>(xt, wqt, wkt, wvt, q, k, v);

    // RoPE: q,k -> q2,k2 (scaled, rounded, d-permuted)
    {
        int tot = BB * LL * (HH + KVH) * (DHH / 2);
        rope2_kernel<<<(tot + 255) / 256, 256>>>(q, k, q2, k2, rc, rs);
    }

    // attention (reads permuted q2/k2, natural v)
    attn_mma_kernel<<<dim3(LL / 64, BB * HH), 128, ATTN_SMEM>>>(q2, k2, v, att);

    // output projection -> d_out
    gemm_wo_kernel<<<dim3(DD / 64, MROWS / 128), 256, GEMM_SMEM>>>(att, wot, out, DD, DD);
}

// round 16
// speedup vs baseline: 1.0683x; 1.0623x over previous
#include <cuda_runtime.h>
#include <math.h>
#include <stdint.h>

#define BB   2
#define LL   2048
#define DD   1024
#define HH   16
#define KVH  4
#define DHH  64
#define GG   (HH / KVH)
#define MROWS (BB * LL)          // 4096

// ---------------- scratch (no allocations allowed) ----------------
__device__ float g_v [MROWS * KVH * DHH];  // v (tf32-rounded)
__device__ float g_q2[MROWS * HH * DHH];   // rope'd, scaled, rounded, d-PERMUTED
__device__ float g_k2[MROWS * KVH * DHH];  // rope'd, rounded, d-PERMUTED
__device__ float g_att[MROWS * HH * DHH];  // attention out (tf32-rounded)
__device__ float g_xt [MROWS * DD];
__device__ float g_wqt[DD * HH * DHH];
__device__ float g_wkt[DD * KVH * DHH];
__device__ float g_wvt[DD * KVH * DHH];
__device__ float g_wot[HH * DHH * DD];

// ---------------- helpers ----------------
__device__ __forceinline__ uint32_t f2tf32(float f) {
    uint32_t u;
    asm("cvt.rna.tf32.f32 %0, %1;" : "=r"(u) : "f"(f));
    return u;
}
__device__ __forceinline__ float rnd_tf32(float f) {
    return __uint_as_float(f2tf32(f));
}

__device__ __forceinline__ void mma_tf32(float* d, const uint32_t* a, const uint32_t* b) {
    asm volatile(
        "mma.sync.aligned.m16n8k8.row.col.f32.tf32.tf32.f32 "
        "{%0,%1,%2,%3}, {%4,%5,%6,%7}, {%8,%9}, {%0,%1,%2,%3};\n"
        : "+f"(d[0]), "+f"(d[1]), "+f"(d[2]), "+f"(d[3])
        : "r"(a[0]), "r"(a[1]), "r"(a[2]), "r"(a[3]), "r"(b[0]), "r"(b[1]));
}

__device__ __forceinline__ uint32_t smaddr(const void* p) {
    return (uint32_t)__cvta_generic_to_shared(p);
}
__device__ __forceinline__ void cp_async16(uint32_t dst, const void* src) {
    asm volatile("cp.async.cg.shared.global [%0], [%1], 16;\n" :: "r"(dst), "l"(src));
}

// d-permutation within each 8-group: orig k -> phys 2*(k&3) + ((k>>2)&1)
__device__ __forceinline__ int dperm(int d) {
    return (d & ~7) | (((d & 3) << 1) | ((d >> 2) & 1));
}

#define QSCALE (0.125f * 1.4426950408889634f)   // softmax scale * log2(e)

// ---------------- prologue: tf32-round x and all weights ----------------
#define X4  (MROWS * DD / 4)
#define WQ4 (DD * HH * DHH / 4)
#define WK4 (DD * KVH * DHH / 4)
#define WV4 WK4
#define WO4 (HH * DHH * DD / 4)
#define TOT4 (X4 + WQ4 + WK4 + WV4 + WO4)

__global__ void round_inputs_kernel(const float4* __restrict__ x,
                                    const float4* __restrict__ wq,
                                    const float4* __restrict__ wk,
                                    const float4* __restrict__ wv,
                                    const float4* __restrict__ wo,
                                    float4* __restrict__ xt, float4* __restrict__ wqt,
                                    float4* __restrict__ wkt, float4* __restrict__ wvt,
                                    float4* __restrict__ wot) {
    int i = blockIdx.x * blockDim.x + threadIdx.x;
    if (i >= TOT4) return;
    const float4* s;
    float4* d;
    int j = i;
    if (j < X4)                    { s = x;  d = xt;  }
    else if ((j -= X4)  < WQ4)     { s = wq; d = wqt; }
    else if ((j -= WQ4) < WK4)     { s = wk; d = wkt; }
    else if ((j -= WK4) < WV4)     { s = wv; d = wvt; }
    else { j -= WV4;                 s = wo; d = wot; }
    float4 v = s[j];
    v.x = rnd_tf32(v.x); v.y = rnd_tf32(v.y);
    v.z = rnd_tf32(v.z); v.w = rnd_tf32(v.w);
    d[j] = v;
}

// ---------------- 2-stage cp.async tf32 GEMM core ----------------
// MODE 0: plain fp32 write to C[row*NB+col]
// MODE 1: tf32-rounded write to C[row*NB+col]
// MODE 2: rope epilogue -> dst[(row*heads+h)*64 + dperm(d)] (q/k tiles; one head per tile)
template <int MODE>
__device__ __forceinline__ void gemm_pipe_core(const float* __restrict__ A,
                                               const float* __restrict__ B,
                                               float* __restrict__ C,
                                               int K, int NB, int n0, int m0,
                                               float* __restrict__ rdst, int heads, int h,
                                               const float* __restrict__ rc,
                                               const float* __restrict__ rs,
                                               float osc) {
    constexpr int BM = 128, BN = 64, BK = 32;
    constexpr int AST = BK + 4;   // 36
    constexpr int BST = BN + 8;   // 72
    extern __shared__ float smf[];
    float* Asb = smf;
    float* Bsb = smf + 2 * BM * AST;

    const int tid  = threadIdx.x;
    const int wid  = tid >> 5;
    const int lane = tid & 31;
    const int warpM = wid & 3;
    const int warpN = wid >> 2;
    const int g = lane >> 2;
    const int t = lane & 3;

    float acc[2][4][4];
#pragma unroll
    for (int i = 0; i < 2; ++i)
#pragma unroll
        for (int j = 0; j < 4; ++j)
#pragma unroll
            for (int r = 0; r < 4; ++r) acc[i][j][r] = 0.f;

    auto issue = [&](int k0, int buf) {
        float* As = Asb + buf * BM * AST;
        float* Bs = Bsb + buf * BK * BST;
#pragma unroll
        for (int i = tid; i < BM * BK / 4; i += 256) {
            int m  = i >> 3;
            int k4 = (i & 7) << 2;
            cp_async16(smaddr(&As[m * AST + k4]),
                       &A[(size_t)(m0 + m) * K + k0 + k4]);
        }
#pragma unroll
        for (int i = tid; i < BK * BN / 4; i += 256) {
            int kk = i >> 4;
            int n4 = (i & 15) << 2;
            cp_async16(smaddr(&Bs[kk * BST + n4]),
                       &B[(size_t)(k0 + kk) * NB + n0 + n4]);
        }
        asm volatile("cp.async.commit_group;\n");
    };

    issue(0, 0);
    int buf = 0;
    for (int k0 = 0; k0 < K; k0 += BK) {
        if (k0 + BK < K) {
            issue(k0 + BK, buf ^ 1);
            asm volatile("cp.async.wait_group 1;\n");
        } else {
            asm volatile("cp.async.wait_group 0;\n");
        }
        __syncthreads();

        const uint32_t* As = (const uint32_t*)(Asb + buf * BM * AST);
        const uint32_t* Bs = (const uint32_t*)(Bsb + buf * BK * BST);
#pragma unroll
        for (int ks = 0; ks < BK / 8; ++ks) {
            uint32_t af[2][4], bf[4][2];
#pragma unroll
            for (int mt = 0; mt < 2; ++mt) {
                int mrow = warpM * 32 + mt * 16 + g;
                int kb = ks * 8 + t;
                af[mt][0] = As[mrow * AST + kb];
                af[mt][1] = As[(mrow + 8) * AST + kb];
                af[mt][2] = As[mrow * AST + kb + 4];
                af[mt][3] = As[(mrow + 8) * AST + kb + 4];
            }
#pragma unroll
            for (int nt = 0; nt < 4; ++nt) {
                int ncol = warpN * 32 + nt * 8 + g;
                int kb = ks * 8 + t;
                bf[nt][0] = Bs[kb * BST + ncol];
                bf[nt][1] = Bs[(kb + 4) * BST + ncol];
            }
#pragma unroll
            for (int mt = 0; mt < 2; ++mt)
#pragma unroll
                for (int nt = 0; nt < 4; ++nt)
                    mma_tf32(acc[mt][nt], af[mt], bf[nt]);
        }
        __syncthreads();
        buf ^= 1;
    }

    if (MODE == 2) {
        // ---- rope epilogue: stage tile, rotate (d, d+32) pairs, permute, round
        constexpr int CST = 68;                 // 128 x 68 floats = 34816 B (fits)
        float* Cs = smf;
#pragma unroll
        for (int mt = 0; mt < 2; ++mt) {
#pragma unroll
            for (int nt = 0; nt < 4; ++nt) {
                int lr  = warpM * 32 + mt * 16 + g;
                int col = warpN * 32 + nt * 8 + t * 2;
                Cs[lr * CST + col]           = acc[mt][nt][0];
                Cs[lr * CST + col + 1]       = acc[mt][nt][1];
                Cs[(lr + 8) * CST + col]     = acc[mt][nt][2];
                Cs[(lr + 8) * CST + col + 1] = acc[mt][nt][3];
            }
        }
        __syncthreads();
#pragma unroll
        for (int p = tid; p < 128 * 32; p += 256) {
            int lr = p >> 5;
            int d  = p & 31;
            float t1 = Cs[lr * CST + d];
            float t2 = Cs[lr * CST + d + 32];
            int r = m0 + lr;
            int l = r & (LL - 1);
            float c = rc[l * 32 + d];
            float s = rs[l * 32 + d];
            int pd = dperm(d);
            size_t ob = ((size_t)r * heads + h) * 64;
            rdst[ob + pd]      = rnd_tf32((t1 * c - t2 * s) * osc);
            rdst[ob + pd + 32] = rnd_tf32((t2 * c + t1 * s) * osc);
        }
    } else {
#pragma unroll
        for (int mt = 0; mt < 2; ++mt) {
#pragma unroll
            for (int nt = 0; nt < 4; ++nt) {
                int row = m0 + warpM * 32 + mt * 16 + g;
                int col = n0 + warpN * 32 + nt * 8 + t * 2;
                float c0 = acc[mt][nt][0], c1 = acc[mt][nt][1];
                float c2 = acc[mt][nt][2], c3 = acc[mt][nt][3];
                if (MODE == 1) {
                    c0 = rnd_tf32(c0); c1 = rnd_tf32(c1);
                    c2 = rnd_tf32(c2); c3 = rnd_tf32(c3);
                }
                *(float2*)&C[(size_t)row * NB + col]       = make_float2(c0, c1);
                *(float2*)&C[(size_t)(row + 8) * NB + col] = make_float2(c2, c3);
            }
        }
    }
}

#define GEMM_SMEM ((2 * 128 * 36 + 2 * 32 * 72) * 4)   // 55296 B

// merged QKV projection with fused rope: 24 n-tiles (16 q, 4 k, 4 v)
__global__ __launch_bounds__(256)
void gemm_qkv_kernel(const float* __restrict__ x,
                     const float* __restrict__ Wq, const float* __restrict__ Wk,
                     const float* __restrict__ Wv,
                     float* __restrict__ q2, float* __restrict__ k2,
                     float* __restrict__ v,
                     const float* __restrict__ rc, const float* __restrict__ rs) {
    const int nt = blockIdx.x;
    const int m0 = blockIdx.y * 128;
    if (nt < 16) {
        gemm_pipe_core<2>(x, Wq, nullptr, DD, 1024, nt * 64, m0,
                          q2, HH, nt, rc, rs, QSCALE);
    } else if (nt < 20) {
        gemm_pipe_core<2>(x, Wk, nullptr, DD, 256, (nt - 16) * 64, m0,
                          k2, KVH, nt - 16, rc, rs, 1.f);
    } else {
        gemm_pipe_core<1>(x, Wv, v, DD, 256, (nt - 20) * 64, m0,
                          nullptr, 0, 0, nullptr, nullptr, 0.f);
    }
}

__global__ __launch_bounds__(256)
void gemm_wo_kernel(const float* __restrict__ A, const float* __restrict__ B,
                    float* __restrict__ C, int K, int NB) {
    gemm_pipe_core<0>(A, B, C, K, NB, blockIdx.x * 64, blockIdx.y * 128,
                      nullptr, 0, 0, nullptr, nullptr, 0.f);
}

// ---------------- tf32 flash attention (R11 structure, proven 193.9 us) ----------------
// SMEM: Ks[64][72] (reused as permuted-P region), Vs[64][72].  36864 B. 4 blocks/SM.
#define KST 72
#define VST 72
#define ATTN_SMEM ((64 * KST + 64 * VST) * 4)   // 36864 B

__global__ __launch_bounds__(128, 4)
void attn_mma_kernel(const float* __restrict__ q, const float* __restrict__ k,
                     const float* __restrict__ v, float* __restrict__ o) {
    extern __shared__ uint32_t sm[];
    uint32_t* Ks = sm;                 // K tile (permuted d), later P tile (permuted cols)
    uint32_t* Vs = sm + 64 * KST;      // V tile (natural layout)

    const int bx  = gridDim.x - 1 - blockIdx.x;   // longest first
    const int bh  = blockIdx.y;
    const int b   = bh / HH;
    const int h   = bh % HH;
    const int kvh = h / GG;
    const int q0  = bx * 64;
    const int tid = threadIdx.x;
    const int wid = tid >> 5;
    const int lane = tid & 31;
    const int g = lane >> 2;
    const int t = lane & 3;

    // ---- stage Q tile (pre-scaled/rounded/permuted) through Ks, extract fragments
    const uint4* qbase = (const uint4*)(q + ((size_t)((b * LL + q0) * HH + h)) * DHH);
#pragma unroll
    for (int i = tid; i < 64 * 64 / 4; i += 128) {
        int row = i >> 4;
        int c4  = i & 15;
        *(uint4*)&Ks[row * KST + c4 * 4] = qbase[row * (HH * DHH / 4) + c4];
    }
    __syncthreads();

    uint32_t qf[8][4];
    {
        int r0 = wid * 16 + g;
#pragma unroll
        for (int ks = 0; ks < 8; ++ks) {
            uint2 u = *(const uint2*)&Ks[r0 * KST + ks * 8 + 2 * t];
            uint2 w = *(const uint2*)&Ks[(r0 + 8) * KST + ks * 8 + 2 * t];
            qf[ks][0] = u.x;
            qf[ks][2] = u.y;
            qf[ks][1] = w.x;
            qf[ks][3] = w.y;
        }
    }
    __syncthreads();     // everyone has Q fragments before Ks is reused

    float o_acc[8][4];
#pragma unroll
    for (int nt = 0; nt < 8; ++nt)
#pragma unroll
        for (int r = 0; r < 4; ++r) o_acc[nt][r] = 0.f;
    float m0 = -INFINITY, m1 = -INFINITY, l0 = 0.f, l1 = 0.f;

    const float* kbase = k + ((size_t)b * LL * KVH + kvh) * DHH;
    const float* vbase = v + ((size_t)b * LL * KVH + kvh) * DHH;
    uint32_t* Pw = Ks + wid * 16 * KST;      // warp-private P slice (inside Ks)
    const int ntiles = bx + 1;
    const int perm0 = (t & 1) * 4 + (t >> 1);

    for (int ti = 0; ti < ntiles; ++ti) {
        const int kb = ti * 64;
        // ---- cp.async K/V tile loads (K data is pre-permuted in d)
#pragma unroll
        for (int i = tid; i < 64 * 64 / 4; i += 128) {
            int row = i >> 4;
            int c4  = i & 15;
            size_t goff = (size_t)(kb + row) * KVH * DHH + c4 * 4;
            cp_async16(smaddr(&Ks[row * KST + c4 * 4]), &kbase[goff]);
            cp_async16(smaddr(&Vs[row * VST + c4 * 4]), &vbase[goff]);
        }
        asm volatile("cp.async.commit_group;\n");
        asm volatile("cp.async.wait_group 0;\n");
        __syncthreads();

        // ---- S' = Qs @ K^T (log2 domain); B fragments via LDS.64
        float s_acc[8][4];
#pragma unroll
        for (int nt = 0; nt < 8; ++nt)
#pragma unroll
            for (int r = 0; r < 4; ++r) s_acc[nt][r] = 0.f;
#pragma unroll
        for (int ks = 0; ks < 8; ++ks) {
            uint32_t bfr[8][2];
#pragma unroll
            for (int nt = 0; nt < 8; ++nt) {
                uint2 w = *(const uint2*)&Ks[(nt * 8 + g) * KST + ks * 8 + 2 * t];
                bfr[nt][0] = w.x;
                bfr[nt][1] = w.y;
            }
#pragma unroll
            for (int nt = 0; nt < 8; ++nt) mma_tf32(s_acc[nt], qf[ks], bfr[nt]);
        }

        const int wr = wid * 16 + g;
        if (ti == ntiles - 1) {
#pragma unroll
            for (int nt = 0; nt < 8; ++nt) {
                int c = nt * 8 + 2 * t;
                if (c > wr)          s_acc[nt][0] = -INFINITY;
                if (c + 1 > wr)      s_acc[nt][1] = -INFINITY;
                if (c > wr + 8)      s_acc[nt][2] = -INFINITY;
                if (c + 1 > wr + 8)  s_acc[nt][3] = -INFINITY;
            }
        }

        // ---- online softmax in exp2 domain
        float tm0 = -INFINITY, tm1 = -INFINITY;
#pragma unroll
        for (int nt = 0; nt < 8; ++nt) {
            tm0 = fmaxf(tm0, fmaxf(s_acc[nt][0], s_acc[nt][1]));
            tm1 = fmaxf(tm1, fmaxf(s_acc[nt][2], s_acc[nt][3]));
        }
        tm0 = fmaxf(tm0, __shfl_xor_sync(0xffffffff, tm0, 1));
        tm0 = fmaxf(tm0, __shfl_xor_sync(0xffffffff, tm0, 2));
        tm1 = fmaxf(tm1, __shfl_xor_sync(0xffffffff, tm1, 1));
        tm1 = fmaxf(tm1, __shfl_xor_sync(0xffffffff, tm1, 2));
        float mn0 = fmaxf(m0, tm0), mn1 = fmaxf(m1, tm1);
        float a0 = exp2f(m0 - mn0), a1 = exp2f(m1 - mn1);
        float ps0 = 0.f, ps1 = 0.f;
#pragma unroll
        for (int nt = 0; nt < 8; ++nt) {
            s_acc[nt][0] = exp2f(s_acc[nt][0] - mn0);
            s_acc[nt][1] = exp2f(s_acc[nt][1] - mn0);
            s_acc[nt][2] = exp2f(s_acc[nt][2] - mn1);
            s_acc[nt][3] = exp2f(s_acc[nt][3] - mn1);
            ps0 += s_acc[nt][0] + s_acc[nt][1];
            ps1 += s_acc[nt][2] + s_acc[nt][3];
        }
        ps0 += __shfl_xor_sync(0xffffffff, ps0, 1);
        ps0 += __shfl_xor_sync(0xffffffff, ps0, 2);
        ps1 += __shfl_xor_sync(0xffffffff, ps1, 1);
        ps1 += __shfl_xor_sync(0xffffffff, ps1, 2);
        l0 = l0 * a0 + ps0;
        l1 = l1 * a1 + ps1;
        m0 = mn0; m1 = mn1;

        __syncthreads();   // all warps done reading Ks (S-phase) before P overwrite

        // ---- write P into Ks (warp-private slice) at PERMUTED column positions
#pragma unroll
        for (int nt = 0; nt < 8; ++nt) {
            int cp0 = nt * 8 + perm0;       // permuted col of (2t)
            Pw[g * KST + cp0]           = f2tf32(s_acc[nt][0]);
            Pw[g * KST + cp0 + 2]       = f2tf32(s_acc[nt][1]);   // permuted col of (2t+1)
            Pw[(g + 8) * KST + cp0]     = f2tf32(s_acc[nt][2]);
            Pw[(g + 8) * KST + cp0 + 2] = f2tf32(s_acc[nt][3]);
        }
        __syncwarp();

        // ---- rescale O, then O += P @ V (P fragments via LDS.64 on permuted layout)
#pragma unroll
        for (int nt = 0; nt < 8; ++nt) {
            o_acc[nt][0] *= a0; o_acc[nt][1] *= a0;
            o_acc[nt][2] *= a1; o_acc[nt][3] *= a1;
        }
#pragma unroll
        for (int ks = 0; ks < 8; ++ks) {
            uint32_t pf[4];
            {
                uint2 p0 = *(const uint2*)&Pw[g * KST + ks * 8 + 2 * t];
                uint2 p1 = *(const uint2*)&Pw[(g + 8) * KST + ks * 8 + 2 * t];
                pf[0] = p0.x;  // (row g,   key ks*8+t)
                pf[2] = p0.y;  // (row g,   key ks*8+t+4)
                pf[1] = p1.x;
                pf[3] = p1.y;
            }
            uint32_t bv[8][2];
#pragma unroll
            for (int nt = 0; nt < 8; ++nt) {
                bv[nt][0] = Vs[(ks * 8 + t) * VST + nt * 8 + g];
                bv[nt][1] = Vs[(ks * 8 + t + 4) * VST + nt * 8 + g];
            }
#pragma unroll
            for (int nt = 0; nt < 8; ++nt) mma_tf32(o_acc[nt], pf, bv[nt]);
        }
        __syncthreads();   // P/V reads done before next tile load
    }

    // ---- epilogue (round att outputs so gemm_wo is CVT-free)
    const float inv0 = 1.f / l0, inv1 = 1.f / l1;
    const int row0 = q0 + wid * 16 + g;
    float* obase  = o + ((size_t)((b * LL + row0) * HH + h)) * DHH;
    float* obase8 = o + ((size_t)((b * LL + row0 + 8) * HH + h)) * DHH;
#pragma unroll
    for (int nt = 0; nt < 8; ++nt) {
        int c = nt * 8 + 2 * t;
        *(float2*)&obase[c]  = make_float2(rnd_tf32(o_acc[nt][0] * inv0),
                                           rnd_tf32(o_acc[nt][1] * inv0));
        *(float2*)&obase8[c] = make_float2(rnd_tf32(o_acc[nt][2] * inv1),
                                           rnd_tf32(o_acc[nt][3] * inv1));
    }
}

// ---------------- launch ----------------
extern "C" void kernel_launch(void* const* d_in, const int* in_sizes, int n_in,
                              void* d_out, int out_size) {
    const float* x  = (const float*)d_in[0];
    const float* rc = (const float*)d_in[1];
    const float* rs = (const float*)d_in[2];
    const float* Wq = (const float*)d_in[3];
    const float* Wk = (const float*)d_in[4];
    const float* Wv = (const float*)d_in[5];
    const float* Wo = (const float*)d_in[6];
    float* out = (float*)d_out;

    float *v, *q2, *k2, *att, *xt, *wqt, *wkt, *wvt, *wot;
    cudaGetSymbolAddress((void**)&v,   g_v);
    cudaGetSymbolAddress((void**)&q2,  g_q2);
    cudaGetSymbolAddress((void**)&k2,  g_k2);
    cudaGetSymbolAddress((void**)&att, g_att);
    cudaGetSymbolAddress((void**)&xt,  g_xt);
    cudaGetSymbolAddress((void**)&wqt, g_wqt);
    cudaGetSymbolAddress((void**)&wkt, g_wkt);
    cudaGetSymbolAddress((void**)&wvt, g_wvt);
    cudaGetSymbolAddress((void**)&wot, g_wot);

    static bool attr_set = false;
    if (!attr_set) {
        cudaFuncSetAttribute(gemm_qkv_kernel,
                             cudaFuncAttributeMaxDynamicSharedMemorySize, GEMM_SMEM);
        cudaFuncSetAttribute(gemm_wo_kernel,
                             cudaFuncAttributeMaxDynamicSharedMemorySize, GEMM_SMEM);
        cudaFuncSetAttribute(attn_mma_kernel,
                             cudaFuncAttributeMaxDynamicSharedMemorySize, ATTN_SMEM);
        attr_set = true;
    }

    // prologue: tf32-round x + weights
    round_inputs_kernel<<<(TOT4 + 255) / 256, 256>>>(
        (const float4*)x, (const float4*)Wq, (const float4*)Wk,
        (const float4*)Wv, (const float4*)Wo,
        (float4*)xt, (float4*)wqt, (float4*)wkt, (float4*)wvt, (float4*)wot);

    // merged QKV projection with FUSED rope (q2/k2 written rope'd+scaled+permuted)
    gemm_qkv_kernel<<<dim3(24, MROWS / 128), 256, GEMM_SMEM>>>(
        xt, wqt, wkt, wvt, q2, k2, v, rc, rs);

    // attention (reads permuted q2/k2, natural v)
    attn_mma_kernel<<<dim3(LL / 64, BB * HH), 128, ATTN_SMEM>>>(q2, k2, v, att);

    // output projection -> d_out
    gemm_wo_kernel<<<dim3(DD / 64, MROWS / 128), 256, GEMM_SMEM>>>(att, wot, out, DD, DD);
}